// round 4
// baseline (speedup 1.0000x reference)
#include <cuda_runtime.h>
#include <math.h>

#define N_NODES 50000
#define D_IN    128
#define D_H     128
#define D_Z     64
#define E_EDGES 800000

#define CHUNK   512
#define NCHUNKS ((N_NODES + CHUNK - 1) / CHUNK)   // 98

// ---- scratch (device globals; sanctioned scratch mechanism) ----
__device__ int   g_cnt      [N_NODES];
__device__ int   g_cursor   [N_NODES];
__device__ int   g_row_start[N_NODES + 1];
__device__ int   g_chunk_sum[NCHUNKS];
__device__ int   g_chunk_off[NCHUNKS];
__device__ int   g_csr_src  [E_EDGES];
__device__ float g_dinv     [N_NODES];
__device__ __align__(16) float g_xw [N_NODES * D_H];   // X @ W1
__device__ __align__(16) float g_h  [N_NODES * D_H];   // hidden (post bias+relu)
__device__ __align__(16) float g_agg[N_NODES * D_H];   // A_norm @ hidden

// ---------------------------------------------------------------------------
// CSR build
// ---------------------------------------------------------------------------
__global__ void k_init() {
    int i = blockIdx.x * blockDim.x + threadIdx.x;
    if (i < N_NODES) { g_cnt[i] = 0; g_cursor[i] = 0; }
}

__global__ void k_count(const int* __restrict__ dst) {
    int e = blockIdx.x * blockDim.x + threadIdx.x;
    if (e < E_EDGES) {
        int d = dst[e];
        if ((unsigned)d < N_NODES) atomicAdd(&g_cnt[d], 1);
    }
}

__global__ void k_chunk_sum() {
    __shared__ int sh[CHUNK];
    int t = threadIdx.x;
    int i = blockIdx.x * CHUNK + t;
    int v = (i < N_NODES) ? g_cnt[i] : 0;
    sh[t] = v;
    __syncthreads();
    for (int off = CHUNK / 2; off > 0; off >>= 1) {
        if (t < off) sh[t] += sh[t + off];
        __syncthreads();
    }
    if (t == 0) g_chunk_sum[blockIdx.x] = sh[0];
}

__global__ void k_scan_chunks() {
    if (threadIdx.x == 0 && blockIdx.x == 0) {
        int run = 0;
        for (int c = 0; c < NCHUNKS; ++c) {
            g_chunk_off[c] = run;
            run += g_chunk_sum[c];
        }
        g_row_start[N_NODES] = run;
    }
}

// exclusive scan within each chunk + chunk offset; also dinv = rsqrt(cnt+1)
__global__ void k_chunk_scan() {
    __shared__ int sh[CHUNK];
    int t = threadIdx.x;
    int i = blockIdx.x * CHUNK + t;
    int v = (i < N_NODES) ? g_cnt[i] : 0;
    sh[t] = v;
    __syncthreads();
    for (int off = 1; off < CHUNK; off <<= 1) {
        int add = (t >= off) ? sh[t - off] : 0;
        __syncthreads();
        sh[t] += add;
        __syncthreads();
    }
    if (i < N_NODES) {
        g_row_start[i] = sh[t] - v + g_chunk_off[blockIdx.x];
        g_dinv[i] = rsqrtf((float)(v + 1));     // +1 self-loop
    }
}

__global__ void k_scatter(const int* __restrict__ src,
                          const int* __restrict__ dst) {
    int e = blockIdx.x * blockDim.x + threadIdx.x;
    if (e >= E_EDGES) return;
    int d = dst[e];
    int s = src[e];
    if ((unsigned)d >= N_NODES || (unsigned)s >= N_NODES) return;
    int pos = g_row_start[d] + atomicAdd(&g_cursor[d], 1);
    g_csr_src[pos] = s;
}

// ---------------------------------------------------------------------------
// GEMM1:  g_xw = x @ W1   [N,128]x[128,128]
// block: 128 threads, 8 rows per block; thread t owns output column t.
// ---------------------------------------------------------------------------
#define G1_ROWS 8
__global__ void k_gemm1(const float* __restrict__ x,
                        const float* __restrict__ W1) {
    __shared__ float xs[G1_ROWS][D_IN];
    const int t    = threadIdx.x;
    const int row0 = blockIdx.x * G1_ROWS;

    {
        const float4* src  = (const float4*)(x + (size_t)row0 * D_IN);
        float4*       dstp = (float4*)&xs[0][0];
        #pragma unroll
        for (int i = t; i < G1_ROWS * D_IN / 4; i += 128)
            dstp[i] = src[i];
    }
    __syncthreads();

    float acc[G1_ROWS];
    #pragma unroll
    for (int r = 0; r < G1_ROWS; ++r) acc[r] = 0.0f;

    #pragma unroll 4
    for (int k = 0; k < D_IN; ++k) {
        float w = W1[k * D_H + t];
        #pragma unroll
        for (int r = 0; r < G1_ROWS; ++r)
            acc[r] = fmaf(xs[r][k], w, acc[r]);
    }

    #pragma unroll
    for (int r = 0; r < G1_ROWS; ++r)
        g_xw[(size_t)(row0 + r) * D_H + t] = acc[r];
}

// ---------------------------------------------------------------------------
// gather-aggregate: one warp per dst node, float4 per lane (32*4 = 128 floats)
//   acc = table[node]*dinv[node]^2 + sum_{s in N(node)} table[s]*dinv[s]*dinv[node]
// LAYER==1: table=g_xw, out=g_h,  epilogue relu(acc + bias)
// LAYER==2: table=g_h,  out=g_agg, no epilogue
// ---------------------------------------------------------------------------
template <int LAYER>
__global__ void k_agg(const float* __restrict__ bias) {
    const float* table = (LAYER == 1) ? g_xw : g_h;
    float*       out   = (LAYER == 1) ? g_h  : g_agg;

    int gtid = blockIdx.x * blockDim.x + threadIdx.x;
    int node = gtid >> 5;
    int lane = gtid & 31;
    if (node >= N_NODES) return;

    const int start = g_row_start[node];
    const int end   = g_row_start[node + 1];
    const float dd  = g_dinv[node];

    // self-loop term
    float4 acc = ((const float4*)(table + (size_t)node * D_H))[lane];
    float sl = dd * dd;
    acc.x *= sl; acc.y *= sl; acc.z *= sl; acc.w *= sl;

    int s = (start < end) ? g_csr_src[start] : 0;
    for (int i = start; i < end; ++i) {
        int s_next = (i + 1 < end) ? g_csr_src[i + 1] : 0;
        float norm = g_dinv[s] * dd;
        float4 v = __ldg(&((const float4*)(table + (size_t)s * D_H))[lane]);
        acc.x = fmaf(v.x, norm, acc.x);
        acc.y = fmaf(v.y, norm, acc.y);
        acc.z = fmaf(v.z, norm, acc.z);
        acc.w = fmaf(v.w, norm, acc.w);
        s = s_next;
    }

    if (LAYER == 1) {
        float4 b = ((const float4*)bias)[lane];
        acc.x = fmaxf(acc.x + b.x, 0.0f);
        acc.y = fmaxf(acc.y + b.y, 0.0f);
        acc.z = fmaxf(acc.z + b.z, 0.0f);
        acc.w = fmaxf(acc.w + b.w, 0.0f);
    }
    ((float4*)(out + (size_t)node * D_H))[lane] = acc;
}

// ---------------------------------------------------------------------------
// GEMM2 + VGAE epilogue:
//   mu = agg@Wmu+bmu ; logstd = agg@Wls+bls ; z = mu + eps*exp(logstd)
// out layout: [z | mu | logstd], each N*64
// ---------------------------------------------------------------------------
#define G2_ROWS 8
__global__ void k_gemm2(const float* __restrict__ Wmu,
                        const float* __restrict__ bmu,
                        const float* __restrict__ Wls,
                        const float* __restrict__ bls,
                        const float* __restrict__ eps,
                        float* __restrict__ out) {
    __shared__ float xs[G2_ROWS][D_H];
    const int t    = threadIdx.x;          // 0..63
    const int row0 = blockIdx.x * G2_ROWS;

    {
        const float4* src  = (const float4*)(g_agg + (size_t)row0 * D_H);
        float4*       dstp = (float4*)&xs[0][0];
        #pragma unroll
        for (int i = t; i < G2_ROWS * D_H / 4; i += 64)
            dstp[i] = src[i];
    }
    __syncthreads();

    float amu[G2_ROWS], als[G2_ROWS];
    #pragma unroll
    for (int r = 0; r < G2_ROWS; ++r) { amu[r] = 0.0f; als[r] = 0.0f; }

    #pragma unroll 4
    for (int k = 0; k < D_H; ++k) {
        float wmu = Wmu[k * D_Z + t];
        float wls = Wls[k * D_Z + t];
        #pragma unroll
        for (int r = 0; r < G2_ROWS; ++r) {
            float xv = xs[r][k];
            amu[r] = fmaf(xv, wmu, amu[r]);
            als[r] = fmaf(xv, wls, als[r]);
        }
    }

    const float bm = bmu[t];
    const float bl = bls[t];
    const size_t seg = (size_t)N_NODES * D_Z;

    #pragma unroll
    for (int r = 0; r < G2_ROWS; ++r) {
        size_t off = (size_t)(row0 + r) * D_Z + t;
        float mu = amu[r] + bm;
        float ls = als[r] + bl;
        float z  = mu + eps[off] * expf(ls);
        out[off]           = z;
        out[seg + off]     = mu;
        out[2 * seg + off] = ls;
    }
}

// ---------------------------------------------------------------------------
extern "C" void kernel_launch(void* const* d_in, const int* in_sizes, int n_in,
                              void* d_out, int out_size) {
    const float* x   = (const float*)d_in[0];
    const int*   ei  = (const int*)d_in[1];     // [2, E] int32 (JAX x64 off!)
    const float* eps = (const float*)d_in[2];
    const float* W1  = (const float*)d_in[3];
    const float* b1  = (const float*)d_in[4];
    const float* Wmu = (const float*)d_in[5];
    const float* bmu = (const float*)d_in[6];
    const float* Wls = (const float*)d_in[7];
    const float* bls = (const float*)d_in[8];
    float*       out = (float*)d_out;

    const int* src = ei;            // row 0
    const int* dst = ei + E_EDGES;  // row 1

    // CSR build + degrees
    k_init       <<<(N_NODES + 255) / 256, 256>>>();
    k_count      <<<(E_EDGES + 255) / 256, 256>>>(dst);
    k_chunk_sum  <<<NCHUNKS, CHUNK>>>();
    k_scan_chunks<<<1, 32>>>();
    k_chunk_scan <<<NCHUNKS, CHUNK>>>();
    k_scatter    <<<(E_EDGES + 255) / 256, 256>>>(src, dst);

    // layer 1: dense transform
    k_gemm1<<<N_NODES / G1_ROWS, 128>>>(x, W1);

    // aggregations (warp per node)
    {
        long long total = (long long)N_NODES * 32;
        int blocks = (int)((total + 255) / 256);
        k_agg<1><<<blocks, 256>>>(b1);       // g_xw -> g_h (bias+relu)
        k_agg<2><<<blocks, 256>>>(nullptr);  // g_h  -> g_agg
    }

    // output GEMMs + reparameterization
    k_gemm2<<<N_NODES / G2_ROWS, 64>>>(Wmu, bmu, Wls, bls, eps, out);
}

// round 5
// speedup vs baseline: 1.1120x; 1.1120x over previous
#include <cuda_runtime.h>
#include <math.h>

#define N_NODES 50000
#define D_IN    128
#define D_H     128
#define D_Z     64
#define E_EDGES 800000

#define CHUNK   512
#define NCHUNKS ((N_NODES + CHUNK - 1) / CHUNK)   // 98

// ---- scratch (device globals; sanctioned scratch mechanism) ----
__device__ int   g_cnt      [N_NODES];
__device__ int   g_cursor   [N_NODES];
__device__ int   g_row_start[N_NODES + 1];
__device__ int   g_chunk_sum[NCHUNKS];
__device__ int   g_chunk_off[NCHUNKS];
__device__ int   g_csr_src  [E_EDGES];
__device__ float g_dinv     [N_NODES];
__device__ __align__(16) float g_xw [N_NODES * D_H];   // X @ W1
__device__ __align__(16) float g_h  [N_NODES * D_H];   // hidden (post bias+relu)
__device__ __align__(16) float g_agg[N_NODES * D_H];   // A_norm @ hidden

// ---------------------------------------------------------------------------
// CSR build
// ---------------------------------------------------------------------------
__global__ void k_init() {
    int i = blockIdx.x * blockDim.x + threadIdx.x;
    if (i < N_NODES) { g_cnt[i] = 0; g_cursor[i] = 0; }
}

__global__ void k_count(const int* __restrict__ dst) {
    int e = blockIdx.x * blockDim.x + threadIdx.x;
    if (e < E_EDGES) {
        int d = dst[e];
        if ((unsigned)d < N_NODES) atomicAdd(&g_cnt[d], 1);
    }
}

__global__ void k_chunk_sum() {
    __shared__ int sh[CHUNK];
    int t = threadIdx.x;
    int i = blockIdx.x * CHUNK + t;
    int v = (i < N_NODES) ? g_cnt[i] : 0;
    sh[t] = v;
    __syncthreads();
    for (int off = CHUNK / 2; off > 0; off >>= 1) {
        if (t < off) sh[t] += sh[t + off];
        __syncthreads();
    }
    if (t == 0) g_chunk_sum[blockIdx.x] = sh[0];
}

// parallel exclusive scan over the 98 chunk sums (1 block, 128 threads)
__global__ void k_scan_chunks() {
    __shared__ int sh[128];
    int t = threadIdx.x;
    int v = (t < NCHUNKS) ? g_chunk_sum[t] : 0;
    sh[t] = v;
    __syncthreads();
    #pragma unroll
    for (int off = 1; off < 128; off <<= 1) {
        int add = (t >= off) ? sh[t - off] : 0;
        __syncthreads();
        sh[t] += add;
        __syncthreads();
    }
    if (t < NCHUNKS) g_chunk_off[t] = sh[t] - v;   // exclusive
    if (t == 127)    g_row_start[N_NODES] = sh[127];
}

// exclusive scan within each chunk + chunk offset; also dinv = rsqrt(cnt+1)
__global__ void k_chunk_scan() {
    __shared__ int sh[CHUNK];
    int t = threadIdx.x;
    int i = blockIdx.x * CHUNK + t;
    int v = (i < N_NODES) ? g_cnt[i] : 0;
    sh[t] = v;
    __syncthreads();
    for (int off = 1; off < CHUNK; off <<= 1) {
        int add = (t >= off) ? sh[t - off] : 0;
        __syncthreads();
        sh[t] += add;
        __syncthreads();
    }
    if (i < N_NODES) {
        g_row_start[i] = sh[t] - v + g_chunk_off[blockIdx.x];
        g_dinv[i] = rsqrtf((float)(v + 1));     // +1 self-loop
    }
}

__global__ void k_scatter(const int* __restrict__ src,
                          const int* __restrict__ dst) {
    int e = blockIdx.x * blockDim.x + threadIdx.x;
    if (e >= E_EDGES) return;
    int d = dst[e];
    int s = src[e];
    if ((unsigned)d >= N_NODES || (unsigned)s >= N_NODES) return;
    int pos = g_row_start[d] + atomicAdd(&g_cursor[d], 1);
    g_csr_src[pos] = s;
}

// ---------------------------------------------------------------------------
// GEMM1:  g_xw = x @ W1   [N,128]x[128,128]
// 128 threads, 8 rows/block; thread t owns column t.
// Inner loop: float4 broadcast LDS on xs -> 44 issue slots / 32 FMA.
// ---------------------------------------------------------------------------
#define G1_ROWS 8
__global__ void k_gemm1(const float* __restrict__ x,
                        const float* __restrict__ W1) {
    __shared__ __align__(16) float xs[G1_ROWS][D_IN];
    const int t    = threadIdx.x;
    const int row0 = blockIdx.x * G1_ROWS;

    {
        const float4* src  = (const float4*)(x + (size_t)row0 * D_IN);
        float4*       dstp = (float4*)&xs[0][0];
        #pragma unroll
        for (int i = t; i < G1_ROWS * D_IN / 4; i += 128)
            dstp[i] = src[i];
    }
    __syncthreads();

    float acc[G1_ROWS];
    #pragma unroll
    for (int r = 0; r < G1_ROWS; ++r) acc[r] = 0.0f;

    #pragma unroll 8
    for (int k4 = 0; k4 < D_IN / 4; ++k4) {
        const int k = k4 * 4;
        float w0 = __ldg(&W1[(k + 0) * D_H + t]);
        float w1 = __ldg(&W1[(k + 1) * D_H + t]);
        float w2 = __ldg(&W1[(k + 2) * D_H + t]);
        float w3 = __ldg(&W1[(k + 3) * D_H + t]);
        #pragma unroll
        for (int r = 0; r < G1_ROWS; ++r) {
            float4 xv = *(const float4*)&xs[r][k];
            acc[r] = fmaf(xv.x, w0, acc[r]);
            acc[r] = fmaf(xv.y, w1, acc[r]);
            acc[r] = fmaf(xv.z, w2, acc[r]);
            acc[r] = fmaf(xv.w, w3, acc[r]);
        }
    }

    #pragma unroll
    for (int r = 0; r < G1_ROWS; ++r)
        g_xw[(size_t)(row0 + r) * D_H + t] = acc[r];
}

// ---------------------------------------------------------------------------
// gather-aggregate: one warp per dst node, float4 per lane.
// Edge loop unrolled x4 for MLP.
// LAYER==1: table=g_xw, out=g_h,  epilogue relu(acc + bias)
// LAYER==2: table=g_h,  out=g_agg
// ---------------------------------------------------------------------------
template <int LAYER>
__global__ void k_agg(const float* __restrict__ bias) {
    const float* table = (LAYER == 1) ? g_xw : g_h;
    float*       out   = (LAYER == 1) ? g_h  : g_agg;

    int gtid = blockIdx.x * blockDim.x + threadIdx.x;
    int node = gtid >> 5;
    int lane = gtid & 31;
    if (node >= N_NODES) return;

    const int start = g_row_start[node];
    const int end   = g_row_start[node + 1];
    const float dd  = g_dinv[node];

    // self-loop term
    float4 acc = ((const float4*)(table + (size_t)node * D_H))[lane];
    float sl = dd * dd;
    acc.x *= sl; acc.y *= sl; acc.z *= sl; acc.w *= sl;

    int i = start;
    for (; i + 4 <= end; i += 4) {
        int s0 = g_csr_src[i + 0];
        int s1 = g_csr_src[i + 1];
        int s2 = g_csr_src[i + 2];
        int s3 = g_csr_src[i + 3];
        float n0 = g_dinv[s0] * dd;
        float n1 = g_dinv[s1] * dd;
        float n2 = g_dinv[s2] * dd;
        float n3 = g_dinv[s3] * dd;
        float4 v0 = __ldg(&((const float4*)(table + (size_t)s0 * D_H))[lane]);
        float4 v1 = __ldg(&((const float4*)(table + (size_t)s1 * D_H))[lane]);
        float4 v2 = __ldg(&((const float4*)(table + (size_t)s2 * D_H))[lane]);
        float4 v3 = __ldg(&((const float4*)(table + (size_t)s3 * D_H))[lane]);
        acc.x = fmaf(v0.x, n0, acc.x); acc.y = fmaf(v0.y, n0, acc.y);
        acc.z = fmaf(v0.z, n0, acc.z); acc.w = fmaf(v0.w, n0, acc.w);
        acc.x = fmaf(v1.x, n1, acc.x); acc.y = fmaf(v1.y, n1, acc.y);
        acc.z = fmaf(v1.z, n1, acc.z); acc.w = fmaf(v1.w, n1, acc.w);
        acc.x = fmaf(v2.x, n2, acc.x); acc.y = fmaf(v2.y, n2, acc.y);
        acc.z = fmaf(v2.z, n2, acc.z); acc.w = fmaf(v2.w, n2, acc.w);
        acc.x = fmaf(v3.x, n3, acc.x); acc.y = fmaf(v3.y, n3, acc.y);
        acc.z = fmaf(v3.z, n3, acc.z); acc.w = fmaf(v3.w, n3, acc.w);
    }
    for (; i < end; ++i) {
        int s = g_csr_src[i];
        float norm = g_dinv[s] * dd;
        float4 v = __ldg(&((const float4*)(table + (size_t)s * D_H))[lane]);
        acc.x = fmaf(v.x, norm, acc.x);
        acc.y = fmaf(v.y, norm, acc.y);
        acc.z = fmaf(v.z, norm, acc.z);
        acc.w = fmaf(v.w, norm, acc.w);
    }

    if (LAYER == 1) {
        float4 b = ((const float4*)bias)[lane];
        acc.x = fmaxf(acc.x + b.x, 0.0f);
        acc.y = fmaxf(acc.y + b.y, 0.0f);
        acc.z = fmaxf(acc.z + b.z, 0.0f);
        acc.w = fmaxf(acc.w + b.w, 0.0f);
    }
    ((float4*)(out + (size_t)node * D_H))[lane] = acc;
}

// ---------------------------------------------------------------------------
// GEMM2 + VGAE epilogue:
//   mu = agg@Wmu+bmu ; logstd = agg@Wls+bls ; z = mu + eps*exp(logstd)
// out layout: [z | mu | logstd], each N*64
// ---------------------------------------------------------------------------
#define G2_ROWS 8
__global__ void k_gemm2(const float* __restrict__ Wmu,
                        const float* __restrict__ bmu,
                        const float* __restrict__ Wls,
                        const float* __restrict__ bls,
                        const float* __restrict__ eps,
                        float* __restrict__ out) {
    __shared__ __align__(16) float xs[G2_ROWS][D_H];
    const int t    = threadIdx.x;          // 0..63
    const int row0 = blockIdx.x * G2_ROWS;

    {
        const float4* src  = (const float4*)(g_agg + (size_t)row0 * D_H);
        float4*       dstp = (float4*)&xs[0][0];
        #pragma unroll
        for (int i = t; i < G2_ROWS * D_H / 4; i += 64)
            dstp[i] = src[i];
    }
    __syncthreads();

    float amu[G2_ROWS], als[G2_ROWS];
    #pragma unroll
    for (int r = 0; r < G2_ROWS; ++r) { amu[r] = 0.0f; als[r] = 0.0f; }

    #pragma unroll 8
    for (int k4 = 0; k4 < D_H / 4; ++k4) {
        const int k = k4 * 4;
        float wm0 = __ldg(&Wmu[(k + 0) * D_Z + t]);
        float wm1 = __ldg(&Wmu[(k + 1) * D_Z + t]);
        float wm2 = __ldg(&Wmu[(k + 2) * D_Z + t]);
        float wm3 = __ldg(&Wmu[(k + 3) * D_Z + t]);
        float wl0 = __ldg(&Wls[(k + 0) * D_Z + t]);
        float wl1 = __ldg(&Wls[(k + 1) * D_Z + t]);
        float wl2 = __ldg(&Wls[(k + 2) * D_Z + t]);
        float wl3 = __ldg(&Wls[(k + 3) * D_Z + t]);
        #pragma unroll
        for (int r = 0; r < G2_ROWS; ++r) {
            float4 xv = *(const float4*)&xs[r][k];
            amu[r] = fmaf(xv.x, wm0, amu[r]);
            amu[r] = fmaf(xv.y, wm1, amu[r]);
            amu[r] = fmaf(xv.z, wm2, amu[r]);
            amu[r] = fmaf(xv.w, wm3, amu[r]);
            als[r] = fmaf(xv.x, wl0, als[r]);
            als[r] = fmaf(xv.y, wl1, als[r]);
            als[r] = fmaf(xv.z, wl2, als[r]);
            als[r] = fmaf(xv.w, wl3, als[r]);
        }
    }

    const float bm = bmu[t];
    const float bl = bls[t];
    const size_t seg = (size_t)N_NODES * D_Z;

    #pragma unroll
    for (int r = 0; r < G2_ROWS; ++r) {
        size_t off = (size_t)(row0 + r) * D_Z + t;
        float mu = amu[r] + bm;
        float ls = als[r] + bl;
        float z  = mu + eps[off] * expf(ls);
        out[off]           = z;
        out[seg + off]     = mu;
        out[2 * seg + off] = ls;
    }
}

// ---------------------------------------------------------------------------
extern "C" void kernel_launch(void* const* d_in, const int* in_sizes, int n_in,
                              void* d_out, int out_size) {
    const float* x   = (const float*)d_in[0];
    const int*   ei  = (const int*)d_in[1];     // [2, E] int32
    const float* eps = (const float*)d_in[2];
    const float* W1  = (const float*)d_in[3];
    const float* b1  = (const float*)d_in[4];
    const float* Wmu = (const float*)d_in[5];
    const float* bmu = (const float*)d_in[6];
    const float* Wls = (const float*)d_in[7];
    const float* bls = (const float*)d_in[8];
    float*       out = (float*)d_out;

    const int* src = ei;            // row 0
    const int* dst = ei + E_EDGES;  // row 1

    // CSR build + degrees
    k_init       <<<(N_NODES + 255) / 256, 256>>>();
    k_count      <<<(E_EDGES + 255) / 256, 256>>>(dst);
    k_chunk_sum  <<<NCHUNKS, CHUNK>>>();
    k_scan_chunks<<<1, 128>>>();
    k_chunk_scan <<<NCHUNKS, CHUNK>>>();
    k_scatter    <<<(E_EDGES + 255) / 256, 256>>>(src, dst);

    // layer 1: dense transform
    k_gemm1<<<N_NODES / G1_ROWS, 128>>>(x, W1);

    // aggregations (warp per node)
    {
        long long total = (long long)N_NODES * 32;
        int blocks = (int)((total + 255) / 256);
        k_agg<1><<<blocks, 256>>>(b1);       // g_xw -> g_h (bias+relu)
        k_agg<2><<<blocks, 256>>>(nullptr);  // g_h  -> g_agg
    }

    // output GEMMs + reparameterization
    k_gemm2<<<N_NODES / G2_ROWS, 64>>>(Wmu, bmu, Wls, bls, eps, out);
}